// round 16
// baseline (speedup 1.0000x reference)
#include <cuda_runtime.h>
#include <cuda_bf16.h>
#include <cstdint>

#define NB 32
#define WPB 8
#define THREADS (WPB * 32)

__device__ __forceinline__ float sqrt_approx(float x) {
    float r;
    asm("sqrt.approx.f32 %0, %1;" : "=f"(r) : "f"(x));   // sqrt.approx(+0)=+0
    return r;
}

__device__ __forceinline__ float fma_sat(float a, float b, float c) {
    float r;
    asm("fma.rn.sat.f32 %0, %1, %2, %3;" : "=f"(r) : "f"(a), "f"(b), "f"(c));
    return r;
}

__device__ __forceinline__ uint64_t policy_evict_last() {
    uint64_t p;
    asm("createpolicy.fractional.L2::evict_last.b64 %0, 1.0;" : "=l"(p));
    return p;
}
__device__ __forceinline__ uint64_t policy_evict_first() {
    uint64_t p;
    asm("createpolicy.fractional.L2::evict_first.b64 %0, 1.0;" : "=l"(p));
    return p;
}

__device__ __forceinline__ float ldg_evict_last(const float* p, uint64_t pol) {
    float v;
    asm("ld.global.L2::cache_hint.f32 %0, [%1], %2;" : "=f"(v) : "l"(p), "l"(pol));
    return v;
}

__global__ __launch_bounds__(THREADS, 6)
void BioTokenMucusSim_kernel(const float* __restrict__ h,
                             const float* __restrict__ W,
                             const float* __restrict__ stim,
                             float* __restrict__ h_out,
                             float* __restrict__ W_out)
{
    // 32KB W tiles (8 pairs) + 4KB h + mbar = ~36.9KB -> 6 blocks/SM, 48 warps
    __shared__ __align__(128) float  wsm[WPB * NB * NB];
    __shared__ __align__(16)  float4 hsm[WPB * NB];
    __shared__ uint64_t mbar_s;

    const int tid  = threadIdx.x;
    const int warp = tid >> 5;
    const int lane = tid & 31;
    const int qr = lane >> 3;            // row-in-group (update pass)
    const int qc = (lane & 7) * 4;       // col offset   (update pass)
    const int pair0 = blockIdx.x * WPB;  // block's first pair (grid exact)
    const int pair  = pair0 + warp;

    const uint32_t mbar = (uint32_t)__cvta_generic_to_shared(&mbar_s);
    const uint64_t pol_in = policy_evict_last();

    // ---- one mbarrier + TWO bulk DMAs for the whole block ----
    if (tid == 0)
        asm volatile("mbarrier.init.shared.b64 [%0], 1;" :: "r"(mbar) : "memory");
    __syncthreads();
    if (tid == 0) {
        asm volatile("mbarrier.arrive.expect_tx.shared.b64 _, [%0], %1;"
                     :: "r"(mbar), "r"(WPB * NB * NB * 4 + WPB * NB * 16) : "memory");
        const uint32_t wdst = (uint32_t)__cvta_generic_to_shared(wsm);
        const uint32_t hdst = (uint32_t)__cvta_generic_to_shared(hsm);
        asm volatile(
            "cp.async.bulk.shared::cluster.global.mbarrier::complete_tx::bytes.L2::cache_hint"
            " [%0], [%1], %2, [%3], %4;"
            :: "r"(wdst), "l"(W + (size_t)pair0 * NB * NB), "r"(WPB * NB * NB * 4),
               "r"(mbar), "l"(pol_in) : "memory");
        asm volatile(
            "cp.async.bulk.shared::cluster.global.mbarrier::complete_tx::bytes.L2::cache_hint"
            " [%0], [%1], %2, [%3], %4;"
            :: "r"(hdst), "l"(h + (size_t)pair0 * NB * 4), "r"(WPB * NB * 16),
               "r"(mbar), "l"(pol_in) : "memory");
    }

    const float s = ldg_evict_last(stim + (size_t)pair * NB + lane, pol_in);

    // ---- sleepy wait (NOT a hot poll): parity 0, acquire ----
    {
        uint32_t done;
        asm volatile(
            "{\n\t.reg .pred p;\n\t"
            "mbarrier.try_wait.parity.acquire.cta.shared::cta.b64 p, [%1], 0;\n\t"
            "selp.b32 %0, 1, 0, p;\n\t}"
            : "=r"(done) : "r"(mbar) : "memory");
        if (!done) {
            asm volatile(
                "{\n\t.reg .pred P1;\n\t"
                "WAIT_LOOP_%=:\n\t"
                "mbarrier.try_wait.parity.acquire.cta.shared::cta.b64 P1, [%0], 0, 0x989680;\n\t"
                "@P1 bra.uni WAIT_DONE_%=;\n\t"
                "bra.uni WAIT_LOOP_%=;\n\t"
                "WAIT_DONE_%=:\n\t}"
                :: "r"(mbar) : "memory");
        }
    }

    float*  ws = wsm + warp * (NB * NB);
    float4* hp = hsm + warp * NB;

    ws[lane * NB + lane] = 0.0f;         // diag := 0 (matvec + implicit update diag)
    __syncwarp();
    const float4 hv = hp[lane];          // consecutive float4: conflict-free

    // ---- masked matvec: rotated column-groups (unpadded tile, conflict-free) ----
    float ifx = 0.f, ify = 0.f, ifz = 0.f, ifw = 0.f, wsum = 0.f;
    #pragma unroll
    for (int t = 0; t < 8; ++t) {
        const int cg = (t + lane) & 7;                       // rotation
        const float4 w4 = *(const float4*)(ws + lane * NB + cg * 4);
        const float wq[4] = {w4.x, w4.y, w4.z, w4.w};
        #pragma unroll
        for (int e = 0; e < 4; ++e) {
            const float4 hj = hp[cg * 4 + e];                // broadcast: 1 wf
            ifx  = fmaf(wq[e], hj.x, ifx);
            ify  = fmaf(wq[e], hj.y, ify);
            ifz  = fmaf(wq[e], hj.z, ifz);
            ifw  = fmaf(wq[e], hj.w, ifw);
            wsum += wq[e];
        }
    }
    const float inv = 1.0f / (wsum + 1e-8f);
    const float En = ifx * inv, Pn = ify * inv, Gn = ifz * inv, Ln = ifw * inv;

    // ---- channel update ----
    const float E = hv.x, P = hv.y, G = hv.z, L = hv.w;
    const float E_new = fma_sat(-0.2f, G, fmaf(-0.4f, P, fmaf(0.3f, s, E)));
    const float P_new = fma_sat(-0.2f, E, fmaf(0.3f, Pn - P, fmaf(0.5f, s, P)));
    const float G_new = fma_sat(-0.3f, P, fmaf(0.2f, Gn - G,
                                fmaf(0.4f * E, 1.0f - P, G)));
    const float good  = 0.5f * En + 0.5f * Gn;
    const float L_new = fma_sat(-0.3f, P, fmaf(0.3f, Ln - L, fmaf(0.4f, good, L)));

    const float4 hn = make_float4(E_new, P_new, G_new, L_new);

    __syncwarp();                        // all matvec reads of hp done
    hp[lane] = hn;                       // publish h_new == h_out staging
    __syncwarp();

    // ---- W-update IN PLACE in smem (diag implicit: wq=0, dist=0) ----
    float4 hj4[4];
    float  lj05[4];
    #pragma unroll
    for (int e = 0; e < 4; ++e) {
        hj4[e]  = hp[qc + e];
        lj05[e] = 0.05f * hj4[e].w;
    }

    #pragma unroll
    for (int t = 0; t < 8; ++t) {
        const int r = t * 4 + qr;
        float4* cell = (float4*)(ws + r * NB + qc);          // contiguous 512B/t
        const float4 w  = *cell;
        const float4 hr = hp[r];
        const float hr05 = 0.05f * hr.w;
        const float wq[4] = {w.x, w.y, w.z, w.w};
        float out[4];
        #pragma unroll
        for (int e = 0; e < 4; ++e) {
            const float dx = hr.x - hj4[e].x, dy = hr.y - hj4[e].y;
            const float dz = hr.z - hj4[e].z, dw = hr.w - hj4[e].w;
            float sq = dx * dx;
            sq = fmaf(dy, dy, sq);
            sq = fmaf(dz, dz, sq);
            sq = fmaf(dw, dw, sq);
            const float dist = sqrt_approx(sq);
            out[e] = fma_sat(hr05 + lj05[e], dist, 0.95f * wq[e]);
        }
        *cell = make_float4(out[0], out[1], out[2], out[3]);
    }

    // ---- block-level TMA bulk stores: W_out 32KB + h_out 4KB ----
    __syncthreads();
    if (tid == 0) {
        asm volatile("fence.proxy.async;" ::: "memory");
        const uint64_t pol_out = policy_evict_first();
        const uint32_t wsrc = (uint32_t)__cvta_generic_to_shared(wsm);
        const uint32_t hsrc = (uint32_t)__cvta_generic_to_shared(hsm);
        asm volatile(
            "cp.async.bulk.global.shared::cta.bulk_group.L2::cache_hint [%0], [%1], %2, %3;"
            :: "l"(W_out + (size_t)pair0 * NB * NB), "r"(wsrc),
               "r"(WPB * NB * NB * 4), "l"(pol_out) : "memory");
        asm volatile(
            "cp.async.bulk.global.shared::cta.bulk_group.L2::cache_hint [%0], [%1], %2, %3;"
            :: "l"(h_out + (size_t)pair0 * NB * 4), "r"(hsrc),
               "r"(WPB * NB * 16), "l"(pol_out) : "memory");
        asm volatile("cp.async.bulk.commit_group;" ::: "memory");
        asm volatile("cp.async.bulk.wait_group 0;" ::: "memory");
    }
    __syncthreads();   // no thread exits while the bulk store may read smem
}

extern "C" void kernel_launch(void* const* d_in, const int* in_sizes, int n_in,
                              void* d_out, int out_size) {
    const float* h    = (const float*)d_in[0];  // [B,S,32,4]
    const float* W    = (const float*)d_in[1];  // [B,S,32,32]
    const float* stim = (const float*)d_in[2];  // [B,S,32]

    const int n_pairs = in_sizes[2] / NB;       // B*S = 16384 (multiple of 8)

    float* h_out = (float*)d_out;                       // h_new first
    float* W_out = (float*)d_out + (size_t)in_sizes[0]; // then W_new

    const int blocks = n_pairs / WPB;                   // 2048, exact
    BioTokenMucusSim_kernel<<<blocks, THREADS>>>(h, W, stim, h_out, W_out);
}

// round 17
// speedup vs baseline: 1.5767x; 1.5767x over previous
#include <cuda_runtime.h>
#include <cuda_bf16.h>
#include <cstdint>

#define NB 32
#define WPB 8
#define THREADS (WPB * 32)
#define STRIDE 36   // padded row; floats [32..35] of row j hold h[j] (overlay)

__device__ __forceinline__ float clamp01(float x) {
    return fminf(fmaxf(x, 0.0f), 1.0f);
}

__device__ __forceinline__ uint64_t policy_evict_last() {
    uint64_t p;
    asm("createpolicy.fractional.L2::evict_last.b64 %0, 1.0;" : "=l"(p));
    return p;
}

__device__ __forceinline__ void cp_async16_el(float* smem_dst, const float* gmem_src,
                                              uint64_t pol) {
    unsigned sa = (unsigned)__cvta_generic_to_shared(smem_dst);
    asm volatile("cp.async.cg.shared.global.L2::cache_hint [%0], [%1], 16, %2;\n"
                 :: "r"(sa), "l"(gmem_src), "l"(pol) : "memory");
}

__device__ __forceinline__ float ldg_evict_last(const float* p, uint64_t pol) {
    float v;
    asm("ld.global.L2::cache_hint.f32 %0, [%1], %2;" : "=f"(v) : "l"(p), "l"(pol));
    return v;
}

__global__ __launch_bounds__(THREADS, 6)
void BioTokenMucusSim_kernel(const float* __restrict__ h,
                             const float* __restrict__ W,
                             const float* __restrict__ stim,
                             float* __restrict__ h_out,
                             float* __restrict__ W_out,
                             int n_pairs)
{
    // 8 warps x 32 rows x 36 floats = 36864 B/block -> 6 blocks/SM, 48 warps
    __shared__ float wsh[WPB][NB * STRIDE];

    const int warp = threadIdx.x >> 5;
    const int lane = threadIdx.x & 31;
    const int pair = blockIdx.x * WPB + warp;
    if (pair >= n_pairs) return;

    const float* Wp = W + (size_t)pair * (NB * NB);
    float* ws = wsh[warp];

    const int qr  = lane >> 3;                      // row-in-group
    // qr-rotated column group: removes the 2-way bank conflict of (qr, lane&7)
    const int qcr = ((((lane & 7) + qr) & 7)) * 4;  // rotated float4 col offset

    const uint64_t pol = policy_evict_last();

    // ---- W tile + h: cp.async with rotated columns (bank-conflict-free STS) ----
    #pragma unroll
    for (int t = 0; t < 8; ++t) {
        const int r = t * 4 + qr;
        cp_async16_el(ws + r * STRIDE + qcr, Wp + r * NB + qcr, pol);
    }
    cp_async16_el(ws + lane * STRIDE + 32, h + (size_t)pair * NB * 4 + lane * 4, pol);
    asm volatile("cp.async.commit_group;\n" ::: "memory");

    const float s = ldg_evict_last(stim + (size_t)pair * NB + lane, pol);

    asm volatile("cp.async.wait_group 0;\n" ::: "memory");
    __syncwarp();

    // diag := 0 (update pass forces it 0 anyway); read own h back
    ws[lane * STRIDE + lane] = 0.0f;
    const float4 hv = *(const float4*)(ws + lane * STRIDE + 32);
    __syncwarp();

    // ---- masked matvec: row from shared, h via 1-wf broadcasts (unchanged) ----
    float ifx = 0.f, ify = 0.f, ifz = 0.f, ifw = 0.f, wsum = 0.f;
    #pragma unroll
    for (int t = 0; t < 8; ++t) {
        const float4 w4 = *(const float4*)(ws + lane * STRIDE + t * 4);
        const float wq[4] = {w4.x, w4.y, w4.z, w4.w};
        #pragma unroll
        for (int e = 0; e < 4; ++e) {
            const int j = t * 4 + e;
            const float4 hj = *(const float4*)(ws + j * STRIDE + 32);
            ifx  += wq[e] * hj.x;
            ify  += wq[e] * hj.y;
            ifz  += wq[e] * hj.z;
            ifw  += wq[e] * hj.w;
            wsum += wq[e];
        }
    }
    const float inv = 1.0f / (wsum + 1e-8f);
    const float En = ifx * inv, Pn = ify * inv, Gn = ifz * inv, Ln = ifw * inv;

    // ---- channel update ----
    const float E = hv.x, P = hv.y, G = hv.z, L = hv.w;
    const float E_new = clamp01(E + 0.3f * s - 0.4f * P - 0.2f * G);
    const float P_new = clamp01(P + 0.5f * s + 0.3f * (Pn - P) - 0.2f * E);
    const float G_new = clamp01(G + 0.4f * E * (1.0f - P) + 0.2f * (Gn - G) - 0.3f * P);
    const float good  = 0.5f * En + 0.5f * Gn;
    const float L_new = clamp01(L + 0.4f * good + 0.3f * (Ln - L) - 0.3f * P);

    const float4 hn = make_float4(E_new, P_new, G_new, L_new);
    __stcs((float4*)(h_out + (size_t)pair * NB * 4) + lane, hn);   // streaming store

    __syncwarp();                                  // matvec h reads done
    *(float4*)(ws + lane * STRIDE + 32) = hn;      // publish h_new
    __syncwarp();

    // ---- fused W-update + streaming store, rotated columns (4-wf reads) ----
    float4 hj4[4];
    #pragma unroll
    for (int e = 0; e < 4; ++e)
        hj4[e] = *(const float4*)(ws + (qcr + e) * STRIDE + 32);

    float* Wo = W_out + (size_t)pair * (NB * NB);
    #pragma unroll
    for (int t = 0; t < 8; ++t) {
        const int r = t * 4 + qr;
        const float4 w  = *(const float4*)(ws + r * STRIDE + qcr);  // conflict-free
        const float4 hr = *(const float4*)(ws + r * STRIDE + 32);   // 1 wf
        const float wq[4] = {w.x, w.y, w.z, w.w};
        float out[4];
        #pragma unroll
        for (int e = 0; e < 4; ++e) {
            const float dx = hr.x - hj4[e].x, dy = hr.y - hj4[e].y;
            const float dz = hr.z - hj4[e].z, dw = hr.w - hj4[e].w;
            const float sq = dx * dx + dy * dy + dz * dz + dw * dw;
            const float dist = (sq > 0.0f) ? sq * rsqrtf(sq) : 0.0f;
            float wn = fmaf(0.05f * (hr.w + hj4[e].w), dist, 0.95f * wq[e]);
            wn = clamp01(wn);
            if (r == qcr + e) wn = 0.0f;            // diagonal
            out[e] = wn;
        }
        __stcs((float4*)(Wo + r * NB + qcr),
               make_float4(out[0], out[1], out[2], out[3]));
    }
}

extern "C" void kernel_launch(void* const* d_in, const int* in_sizes, int n_in,
                              void* d_out, int out_size) {
    const float* h    = (const float*)d_in[0];  // [B,S,32,4]
    const float* W    = (const float*)d_in[1];  // [B,S,32,32]
    const float* stim = (const float*)d_in[2];  // [B,S,32]

    const int n_pairs = in_sizes[2] / NB;       // B*S = 16384

    float* h_out = (float*)d_out;                       // h_new first
    float* W_out = (float*)d_out + (size_t)in_sizes[0]; // then W_new

    const int blocks = (n_pairs + WPB - 1) / WPB;       // 2048
    BioTokenMucusSim_kernel<<<blocks, THREADS>>>(h, W, stim, h_out, W_out, n_pairs);
}